// round 13
// baseline (speedup 1.0000x reference)
#include <cuda_runtime.h>
#include <cuda_fp16.h>
#include <cstdint>

#define NND 100000
#define NED 3200000
#define HD  64
#define FIN 12
#define EPSBN 1e-5f

// ---------------- static device scratch (no allocations allowed) ----------------
__device__ __align__(256) float  g_bufA[NND * HD];  // fp32 node features (gemm in / agg out)
__device__ __align__(256) __half g_bufH[NND * HD];  // fp16 gemm output (gather table)
__device__ float g_dinv[NND];
__device__ int   g_counts[NND];
__device__ int   g_offsets[NND + 1];
__device__ __align__(16) int g_pos[NED];            // per-edge position within its dst bucket
__device__ __align__(256) int2 g_csr[NED];          // (src, bitcast dinv[src])
__device__ float g_sums[4 * 128];                   // BN partials per layer slot
__device__ int   g_partials[128];                   // scan partials
__device__ int   g_is64;                            // edge_index dtype flag

// ---------------- f32x2 packed-FMA helpers (bit-exact dual fp32) ----------------
__device__ __forceinline__ unsigned long long pack2(float lo, float hi) {
    unsigned long long r;
    asm("mov.b64 %0, {%1, %2};" : "=l"(r) : "f"(lo), "f"(hi));
    return r;
}
__device__ __forceinline__ unsigned long long fma2(unsigned long long a, unsigned long long b,
                                                   unsigned long long c) {
    unsigned long long d;
    asm("fma.rn.f32x2 %0, %1, %2, %3;" : "=l"(d) : "l"(a), "l"(b), "l"(c));
    return d;
}
__device__ __forceinline__ float2 unpack2(unsigned long long v) {
    float2 f;
    asm("mov.b64 {%0, %1}, %2;" : "=f"(f.x), "=f"(f.y) : "l"(v));
    return f;
}

// ---------------- init (+dtype detect folded in) ----------------
__global__ void k_init(const int* ei32) {
    int i = blockIdx.x * blockDim.x + threadIdx.x;
    if (i < NND) g_counts[i] = 0;
    if (i < 4 * 128) g_sums[i] = 0.f;
    if (i == 0) {
        g_offsets[NND] = NED;
        int all0 = 1;
        #pragma unroll
        for (int k = 0; k < 32; k++) {
            if (ei32[2 * k + 1] != 0) all0 = 0;
        }
        g_is64 = all0;
    }
}

// ------- degree histogram: 4 edges/thread, vector loads -------
__global__ void k_hist(const void* ei_) {
    int t4 = blockIdx.x * blockDim.x + threadIdx.x;
    if (t4 >= NED / 4) return;
    int e = t4 * 4;
    int d0, d1, d2, d3;
    if (g_is64) {
        const longlong2* p = (const longlong2*)((const long long*)ei_ + NED + e);
        longlong2 a = p[0], b = p[1];
        d0 = (int)a.x; d1 = (int)a.y; d2 = (int)b.x; d3 = (int)b.y;
    } else {
        int4 a = *(const int4*)((const int*)ei_ + NED + e);
        d0 = a.x; d1 = a.y; d2 = a.z; d3 = a.w;
    }
    int4 p;
    p.x = atomicAdd(&g_counts[d0], 1);
    p.y = atomicAdd(&g_counts[d1], 1);
    p.z = atomicAdd(&g_counts[d2], 1);
    p.w = atomicAdd(&g_counts[d3], 1);
    *(int4*)&g_pos[e] = p;
}

// ---------------- per-1024-chunk totals ----------------
__global__ void k_scan_a() {
    __shared__ int ws[32];
    int t = threadIdx.x;
    int i = blockIdx.x * 1024 + t;
    int v = (i < NND) ? g_counts[i] : 0;
    #pragma unroll
    for (int o = 16; o; o >>= 1) v += __shfl_xor_sync(0xffffffffu, v, o);
    if ((t & 31) == 0) ws[t >> 5] = v;
    __syncthreads();
    if (t < 32) {
        int x = ws[t];
        #pragma unroll
        for (int o = 16; o; o >>= 1) x += __shfl_xor_sync(0xffffffffu, x, o);
        if (t == 0) g_partials[blockIdx.x] = x;
    }
}

// ---------------- block-local scan; block base = sum of preceding partials ----------------
__global__ void k_scan_c() {
    __shared__ int s[2][1024];
    __shared__ int base_sh;
    int t = threadIdx.x;
    int bid = blockIdx.x;
    if (t < 32) {
        int x = 0;
        #pragma unroll
        for (int rep = 0; rep < 4; rep++) {
            int j = rep * 32 + t;
            if (j < bid && j < 98) x += g_partials[j];
        }
        #pragma unroll
        for (int o = 16; o; o >>= 1) x += __shfl_xor_sync(0xffffffffu, x, o);
        if (t == 0) base_sh = x;
    }
    int i = bid * 1024 + t;
    int v = (i < NND) ? g_counts[i] : 0;
    s[0][t] = v;
    __syncthreads();
    int pin = 0;
    #pragma unroll
    for (int off = 1; off < 1024; off <<= 1) {
        int x = s[pin][t];
        if (t >= off) x += s[pin][t - off];
        s[pin ^ 1][t] = x;
        __syncthreads();
        pin ^= 1;
    }
    if (i < NND) {
        g_offsets[i] = s[pin][t] - v + base_sh;
        g_dinv[i] = rsqrtf((float)v + 1.0f);
    }
}

// -------- CSR scatter: 4 edges/thread, atomic-free (positions from hist) --------
__global__ void k_scatter(const void* ei_) {
    int t4 = blockIdx.x * blockDim.x + threadIdx.x;
    if (t4 >= NED / 4) return;
    int e = t4 * 4;
    int s0, s1, s2, s3, d0, d1, d2, d3;
    if (g_is64) {
        const longlong2* ps = (const longlong2*)((const long long*)ei_ + e);
        const longlong2* pd = (const longlong2*)((const long long*)ei_ + NED + e);
        longlong2 sa = ps[0], sb = ps[1], da = pd[0], db = pd[1];
        s0 = (int)sa.x; s1 = (int)sa.y; s2 = (int)sb.x; s3 = (int)sb.y;
        d0 = (int)da.x; d1 = (int)da.y; d2 = (int)db.x; d3 = (int)db.y;
    } else {
        int4 sa = *(const int4*)((const int*)ei_ + e);
        int4 da = *(const int4*)((const int*)ei_ + NED + e);
        s0 = sa.x; s1 = sa.y; s2 = sa.z; s3 = sa.w;
        d0 = da.x; d1 = da.y; d2 = da.z; d3 = da.w;
    }
    int4 p = *(const int4*)&g_pos[e];
    g_csr[g_offsets[d0] + p.x] = make_int2(s0, __float_as_int(g_dinv[s0]));
    g_csr[g_offsets[d1] + p.y] = make_int2(s1, __float_as_int(g_dinv[s1]));
    g_csr[g_offsets[d2] + p.z] = make_int2(s2, __float_as_int(g_dinv[s2]));
    g_csr[g_offsets[d3] + p.w] = make_int2(s3, __float_as_int(g_dinv[s3]));
}

// ---------------- input transform: h0 = relu(x @ W_in + b_in) ----------------
__global__ void k_input(const float* __restrict__ x, const float* __restrict__ Win,
                        const float* __restrict__ bin) {
    int gid = blockIdx.x * blockDim.x + threadIdx.x;
    int node = gid >> 4;
    int q = (gid & 15) * 4;
    if (node >= NND) return;
    float4 acc = *(const float4*)&bin[q];
    #pragma unroll
    for (int k = 0; k < FIN; k++) {
        float xv = __ldg(&x[node * FIN + k]);
        float4 w = *(const float4*)&Win[k * HD + q];
        acc.x += xv * w.x; acc.y += xv * w.y; acc.z += xv * w.z; acc.w += xv * w.w;
    }
    acc.x = fmaxf(acc.x, 0.f); acc.y = fmaxf(acc.y, 0.f);
    acc.z = fmaxf(acc.z, 0.f); acc.w = fmaxf(acc.w, 0.f);
    *(float4*)&g_bufA[node * HD + q] = acc;
}

// ------- GEMM: bufH = (relu(BN(bufA)) @ W) as fp16 (128-thread FFMA2 version) -------
__global__ __launch_bounds__(128, 4) void k_gemm(const float* __restrict__ W,
                                                 const float* __restrict__ gam,
                                                 const float* __restrict__ bet,
                                                 int slot) {
    __shared__ float As[64][128];
    __shared__ float Ws[64 * 64];
    __shared__ float s_scl[64], s_sft[64];
    int t = threadIdx.x;
    if (t < 64) {
        if (slot == 0) {
            s_scl[t] = 1.f; s_sft[t] = 0.f;
        } else {
            float mu  = g_sums[slot * 128 + t] * (1.0f / (float)NND);
            float var = g_sums[slot * 128 + 64 + t] * (1.0f / (float)NND) - mu * mu;
            float scl = gam[t] * rsqrtf(var + EPSBN);
            s_scl[t] = scl;
            s_sft[t] = bet[t] - mu * scl;
        }
    }
    {
        float4* Wsv = (float4*)Ws;
        const float4* Wv = (const float4*)W;
        #pragma unroll
        for (int i = 0; i < 8; i++) Wsv[t + i * 128] = Wv[t + i * 128];
    }
    __syncthreads();

    int base = blockIdx.x * 128;
    int node = base + t;
    if (node < NND) {
        const float4* arow = (const float4*)&g_bufA[node * 64];
        #pragma unroll
        for (int kk = 0; kk < 16; kk++) {
            float4 a = arow[kk];
            int k = kk * 4;
            a.x = fmaxf(a.x * s_scl[k + 0] + s_sft[k + 0], 0.f);
            a.y = fmaxf(a.y * s_scl[k + 1] + s_sft[k + 1], 0.f);
            a.z = fmaxf(a.z * s_scl[k + 2] + s_sft[k + 2], 0.f);
            a.w = fmaxf(a.w * s_scl[k + 3] + s_sft[k + 3], 0.f);
            As[k + 0][t] = a.x; As[k + 1][t] = a.y; As[k + 2][t] = a.z; As[k + 3][t] = a.w;
        }
    } else {
        #pragma unroll
        for (int kk = 0; kk < 16; kk++) {
            int k = kk * 4;
            As[k + 0][t] = 0.f; As[k + 1][t] = 0.f; As[k + 2][t] = 0.f; As[k + 3][t] = 0.f;
        }
    }
    __syncthreads();

    int tx = t & 7, ty = t >> 3;
    int c0 = tx * 8, n0 = ty * 8;
    unsigned long long acc2[4][8];                  // [row-pair ip][col j]
    #pragma unroll
    for (int i = 0; i < 4; i++)
        #pragma unroll
        for (int j = 0; j < 8; j++) acc2[i][j] = 0ull;

    #pragma unroll 8
    for (int k = 0; k < 64; k++) {
        ulonglong2 ap0 = *(const ulonglong2*)&As[k][n0];      // rows (0,1),(2,3)
        ulonglong2 ap1 = *(const ulonglong2*)&As[k][n0 + 4];  // rows (4,5),(6,7)
        float4 w0 = *(const float4*)&Ws[k * 64 + c0];
        float4 w1 = *(const float4*)&Ws[k * 64 + c0 + 4];
        unsigned long long ap[4] = {ap0.x, ap0.y, ap1.x, ap1.y};
        float wv[8] = {w0.x, w0.y, w0.z, w0.w, w1.x, w1.y, w1.z, w1.w};
        #pragma unroll
        for (int j = 0; j < 8; j++) {
            unsigned long long wd = pack2(wv[j], wv[j]);
            #pragma unroll
            for (int ip = 0; ip < 4; ip++)
                acc2[ip][j] = fma2(ap[ip], wd, acc2[ip][j]);
        }
    }

    #pragma unroll
    for (int ip = 0; ip < 4; ip++) {
        float rA[8], rB[8];
        #pragma unroll
        for (int j = 0; j < 8; j++) {
            float2 p = unpack2(acc2[ip][j]);
            rA[j] = p.x; rB[j] = p.y;
        }
        int nA = base + n0 + 2 * ip;
        if (nA < NND) {
            __half2 hs[4];
            hs[0] = __float22half2_rn(make_float2(rA[0], rA[1]));
            hs[1] = __float22half2_rn(make_float2(rA[2], rA[3]));
            hs[2] = __float22half2_rn(make_float2(rA[4], rA[5]));
            hs[3] = __float22half2_rn(make_float2(rA[6], rA[7]));
            *(uint4*)&g_bufH[nA * 64 + c0] = *(const uint4*)hs;
        }
        if (nA + 1 < NND) {
            __half2 hs[4];
            hs[0] = __float22half2_rn(make_float2(rB[0], rB[1]));
            hs[1] = __float22half2_rn(make_float2(rB[2], rB[3]));
            hs[2] = __float22half2_rn(make_float2(rB[4], rB[5]));
            hs[3] = __float22half2_rn(make_float2(rB[6], rB[7]));
            *(uint4*)&g_bufH[(nA + 1) * 64 + c0] = *(const uint4*)hs;
        }
    }
}

// ---- aggregation (+fused BN stats): half-warp-per-edge, 16-deep batches ----
// lanes 0-15 service even edges, 16-31 odd edges; each lane loads 8B (4 fp16 cols).
// 16 edges in flight per sub-batch -> 16 outstanding 128B lines per warp (2x R11).
__global__ __launch_bounds__(256) void k_agg(const float* __restrict__ bias, int slot) {
    __shared__ float s_red[128 * 9];        // col c at s_red[c*9 + warp]
    int t = threadIdx.x;
    int w = t >> 5;
    int lane = t & 31;
    int half = lane >> 4;                   // 0: even edges, 1: odd edges
    int cl = (lane & 15) * 4;               // 4-column base this lane owns
    int wid = (blockIdx.x * blockDim.x + t) >> 5;
    const __half* __restrict__ T = g_bufH;

    int beg = g_offsets[wid];
    int end = g_offsets[wid + 1];
    float a0 = 0.f, a1 = 0.f, a2 = 0.f, a3 = 0.f;

    for (int e0 = beg; e0 < end; e0 += 32) {
        int e = e0 + lane;
        int2 sw = (e < end) ? g_csr[e] : make_int2(0, 0);
        int cnt = end - e0;                  // >0; may exceed 32
        #pragma unroll
        for (int jb = 0; jb < 2; jb++) {
            if (jb * 16 >= cnt) break;       // only skips when cnt <= 16
            int ss[8]; float ww[8]; uint2 hv[8];
            #pragma unroll
            for (int u = 0; u < 8; u++) {
                int j = jb * 16 + 2 * u + half;   // per-lane source index
                ss[u] = __shfl_sync(0xffffffffu, sw.x, j);
                ww[u] = __int_as_float(__shfl_sync(0xffffffffu, sw.y, j));
            }
            #pragma unroll
            for (int u = 0; u < 8; u++)
                hv[u] = *(const uint2*)&T[ss[u] * 64 + cl];
            #pragma unroll
            for (int u = 0; u < 8; u++) {
                float2 v01 = __half22float2(__halves2half2(((const __half*)&hv[u])[0],
                                                           ((const __half*)&hv[u])[1]));
                float2 v23 = __half22float2(__halves2half2(((const __half*)&hv[u])[2],
                                                           ((const __half*)&hv[u])[3]));
                a0 = fmaf(ww[u], v01.x, a0);
                a1 = fmaf(ww[u], v01.y, a1);
                a2 = fmaf(ww[u], v23.x, a2);
                a3 = fmaf(ww[u], v23.y, a3);
            }
        }
    }

    // combine even-edge and odd-edge halves (both halves end with the full sum)
    a0 += __shfl_xor_sync(0xffffffffu, a0, 16);
    a1 += __shfl_xor_sync(0xffffffffu, a1, 16);
    a2 += __shfl_xor_sync(0xffffffffu, a2, 16);
    a3 += __shfl_xor_sync(0xffffffffu, a3, 16);

    float dn = g_dinv[wid];
    float sn = dn * dn;
    uint2 selfraw = *(const uint2*)&T[wid * 64 + cl];
    float2 s01 = __half22float2(__halves2half2(((const __half*)&selfraw)[0],
                                               ((const __half*)&selfraw)[1]));
    float2 s23 = __half22float2(__halves2half2(((const __half*)&selfraw)[2],
                                               ((const __half*)&selfraw)[3]));
    float4 b = *(const float4*)&bias[cl];
    float4 o;
    o.x = dn * a0 + sn * s01.x + b.x;
    o.y = dn * a1 + sn * s01.y + b.y;
    o.z = dn * a2 + sn * s23.x + b.z;
    o.w = dn * a3 + sn * s23.y + b.w;
    if (half == 0) *(float4*)&g_bufA[wid * 64 + cl] = o;

    // BN stats (half 0 only), padded STS tree, 128 global atomics/block
    if (half == 0) {
        s_red[(cl + 0) * 9 + w] = o.x;
        s_red[(cl + 1) * 9 + w] = o.y;
        s_red[(cl + 2) * 9 + w] = o.z;
        s_red[(cl + 3) * 9 + w] = o.w;
        s_red[(64 + cl + 0) * 9 + w] = o.x * o.x;
        s_red[(64 + cl + 1) * 9 + w] = o.y * o.y;
        s_red[(64 + cl + 2) * 9 + w] = o.z * o.z;
        s_red[(64 + cl + 3) * 9 + w] = o.w * o.w;
    }
    __syncthreads();
    if (t < 128) {
        float s = 0.f;
        #pragma unroll
        for (int u = 0; u < 8; u++) s += s_red[t * 9 + u];
        atomicAdd(&g_sums[slot * 128 + t], s);
    }
}

// -------- classifier head: out = relu(BN(bufA) @ Wc1 + bc1) @ Wc2 + bc2 --------
__global__ void k_cls(const float* __restrict__ Wc1, const float* __restrict__ bc1,
                      const float* __restrict__ Wc2, const float* __restrict__ bc2,
                      const float* __restrict__ gam, const float* __restrict__ bet,
                      float* __restrict__ out) {
    __shared__ float w1[64 * 32];
    __shared__ float sscl[64], ssft[64], sb1[32], w2s[64], b2s[2];
    int t = threadIdx.x;
    for (int i = t; i < 2048; i += blockDim.x) w1[i] = Wc1[i];
    if (t < 64) {
        float mu  = g_sums[3 * 128 + t] * (1.0f / (float)NND);
        float var = g_sums[3 * 128 + 64 + t] * (1.0f / (float)NND) - mu * mu;
        float scl = gam[t] * rsqrtf(var + EPSBN);
        sscl[t] = scl;
        ssft[t] = bet[t] - mu * scl;
        w2s[t] = Wc2[t];
    }
    if (t < 32) sb1[t] = bc1[t];
    if (t < 2)  b2s[t] = bc2[t];
    __syncthreads();

    int wid = (blockIdx.x * blockDim.x + t) >> 5;
    if (wid >= NND) return;
    int lane = t & 31;

    float2 v = *(const float2*)&g_bufA[wid * 64 + 2 * lane];
    v.x = v.x * sscl[2 * lane + 0] + ssft[2 * lane + 0];
    v.y = v.y * sscl[2 * lane + 1] + ssft[2 * lane + 1];

    float u = sb1[lane];
    #pragma unroll
    for (int p = 0; p < 32; p++) {
        float a = __shfl_sync(0xffffffffu, v.x, p);
        float b = __shfl_sync(0xffffffffu, v.y, p);
        u = fmaf(a, w1[(2 * p + 0) * 32 + lane], u);
        u = fmaf(b, w1[(2 * p + 1) * 32 + lane], u);
    }
    u = fmaxf(u, 0.f);

    float o0 = fmaf(u, w2s[lane * 2 + 0], b2s[0] * (1.0f / 32.0f));
    float o1 = fmaf(u, w2s[lane * 2 + 1], b2s[1] * (1.0f / 32.0f));
    #pragma unroll
    for (int off = 16; off; off >>= 1) {
        o0 += __shfl_xor_sync(0xffffffffu, o0, off);
        o1 += __shfl_xor_sync(0xffffffffu, o1, off);
    }
    if (lane == 0) {
        out[wid * 2 + 0] = o0;
        out[wid * 2 + 1] = o1;
    }
}

// ---------------- host launch sequence (graph-capturable, two-stream fork-join) ----------------
extern "C" void kernel_launch(void* const* d_in, const int* in_sizes, int n_in,
                              void* d_out, int out_size) {
    const float* x     = (const float*)d_in[0];
    const void*  ei    = d_in[1];
    const float* Win   = (const float*)d_in[2];
    const float* bin   = (const float*)d_in[3];
    const float* Wg    = (const float*)d_in[4];   // [3,64,64]
    const float* bg    = (const float*)d_in[5];   // [3,64]
    const float* gamma = (const float*)d_in[6];   // [3,64]
    const float* beta  = (const float*)d_in[7];   // [3,64]
    const float* Wc1   = (const float*)d_in[8];
    const float* bc1   = (const float*)d_in[9];
    const float* Wc2   = (const float*)d_in[10];
    const float* bc2   = (const float*)d_in[11];
    float* out = (float*)d_out;

    // Created once on the first (uncaptured, correctness) call; reused during capture.
    static cudaStream_t s2 = nullptr;
    static cudaEvent_t evFork = nullptr, evJoin = nullptr;
    if (s2 == nullptr) {
        cudaStreamCreateWithFlags(&s2, cudaStreamNonBlocking);
        cudaEventCreateWithFlags(&evFork, cudaEventDisableTiming);
        cudaEventCreateWithFlags(&evJoin, cudaEventDisableTiming);
    }

    // Fork: side stream does the dense path (input + gemm0) while the main
    // stream builds the CSR (hist/scan/scatter) — disjoint buffers, disjoint pipes.
    cudaEventRecord(evFork, 0);
    cudaStreamWaitEvent(s2, evFork, 0);
    k_input<<<(NND * 16 + 255) / 256, 256, 0, s2>>>(x, Win, bin);
    k_gemm<<<(NND + 127) / 128, 128, 0, s2>>>(Wg, gamma, beta, 0);
    cudaEventRecord(evJoin, s2);

    k_init<<<(NND + 255) / 256, 256>>>((const int*)ei);
    k_hist<<<(NED / 4 + 255) / 256, 256>>>(ei);
    k_scan_a<<<98, 1024>>>();
    k_scan_c<<<98, 1024>>>();
    k_scatter<<<(NED / 4 + 255) / 256, 256>>>(ei);

    cudaStreamWaitEvent(0, evJoin, 0);           // join before first aggregation

    k_agg<<<NND / 8, 256>>>(bg, 1);
    k_gemm<<<(NND + 127) / 128, 128>>>(Wg + 4096, gamma, beta, 1);
    k_agg<<<NND / 8, 256>>>(bg + 64, 2);
    k_gemm<<<(NND + 127) / 128, 128>>>(Wg + 8192, gamma + 64, beta + 64, 2);
    k_agg<<<NND / 8, 256>>>(bg + 128, 3);

    k_cls<<<NND / 8, 256>>>(Wc1, bc1, Wc2, bc2, gamma + 128, beta + 128, out);
}

// round 14
// speedup vs baseline: 1.0518x; 1.0518x over previous
#include <cuda_runtime.h>
#include <cuda_fp16.h>
#include <cstdint>

#define NND 100000
#define NED 3200000
#define HD  64
#define FIN 12
#define EPSBN 1e-5f

// ---------------- static device scratch (no allocations allowed) ----------------
__device__ __align__(256) float  g_bufA[NND * HD];        // fp32 node features
__device__ __align__(256) __half g_bufH[(NND + 8) * HD];  // fp16 table; row NND stays ZERO (pad row)
__device__ float g_dinv[NND];
__device__ int   g_counts[NND];
__device__ int   g_offsets[NND + 1];
__device__ __align__(16) int g_pk[NED];             // packed (dst | pos<<17) per edge
__device__ __align__(256) int g_csr[NED];           // src only (table is dinv-prescaled)
__device__ float g_sums[4 * 128];                   // BN partials per layer slot
__device__ int   g_partials[128];                   // scan partials
__device__ int   g_is64;                            // edge_index dtype flag

// ---------------- f32x2 packed-FMA helpers (bit-exact dual fp32) ----------------
__device__ __forceinline__ unsigned long long pack2(float lo, float hi) {
    unsigned long long r;
    asm("mov.b64 %0, {%1, %2};" : "=l"(r) : "f"(lo), "f"(hi));
    return r;
}
__device__ __forceinline__ unsigned long long fma2(unsigned long long a, unsigned long long b,
                                                   unsigned long long c) {
    unsigned long long d;
    asm("fma.rn.f32x2 %0, %1, %2, %3;" : "=l"(d) : "l"(a), "l"(b), "l"(c));
    return d;
}
__device__ __forceinline__ float2 unpack2(unsigned long long v) {
    float2 f;
    asm("mov.b64 {%0, %1}, %2;" : "=f"(f.x), "=f"(f.y) : "l"(v));
    return f;
}

// ---------------- init (+dtype detect folded in) ----------------
__global__ void k_init(const int* ei32) {
    int i = blockIdx.x * blockDim.x + threadIdx.x;
    if (i < NND) g_counts[i] = 0;
    if (i < 4 * 128) g_sums[i] = 0.f;
    if (i == 0) {
        g_offsets[NND] = NED;
        int all0 = 1;
        #pragma unroll
        for (int k = 0; k < 32; k++) {
            if (ei32[2 * k + 1] != 0) all0 = 0;
        }
        g_is64 = all0;
    }
}

// ------- degree histogram: 4 edges/thread; writes packed (dst | pos<<17) -------
__global__ void k_hist(const void* ei_) {
    int t4 = blockIdx.x * blockDim.x + threadIdx.x;
    if (t4 >= NED / 4) return;
    int e = t4 * 4;
    int d0, d1, d2, d3;
    if (g_is64) {
        const longlong2* p = (const longlong2*)((const long long*)ei_ + NED + e);
        longlong2 a = p[0], b = p[1];
        d0 = (int)a.x; d1 = (int)a.y; d2 = (int)b.x; d3 = (int)b.y;
    } else {
        int4 a = *(const int4*)((const int*)ei_ + NED + e);
        d0 = a.x; d1 = a.y; d2 = a.z; d3 = a.w;
    }
    int4 p;
    p.x = d0 | (atomicAdd(&g_counts[d0], 1) << 17);
    p.y = d1 | (atomicAdd(&g_counts[d1], 1) << 17);
    p.z = d2 | (atomicAdd(&g_counts[d2], 1) << 17);
    p.w = d3 | (atomicAdd(&g_counts[d3], 1) << 17);
    *(int4*)&g_pk[e] = p;
}

// ---------------- per-1024-chunk totals ----------------
__global__ void k_scan_a() {
    __shared__ int ws[32];
    int t = threadIdx.x;
    int i = blockIdx.x * 1024 + t;
    int v = (i < NND) ? g_counts[i] : 0;
    #pragma unroll
    for (int o = 16; o; o >>= 1) v += __shfl_xor_sync(0xffffffffu, v, o);
    if ((t & 31) == 0) ws[t >> 5] = v;
    __syncthreads();
    if (t < 32) {
        int x = ws[t];
        #pragma unroll
        for (int o = 16; o; o >>= 1) x += __shfl_xor_sync(0xffffffffu, x, o);
        if (t == 0) g_partials[blockIdx.x] = x;
    }
}

// ---------------- block-local scan; block base = sum of preceding partials ----------------
__global__ void k_scan_c() {
    __shared__ int s[2][1024];
    __shared__ int base_sh;
    int t = threadIdx.x;
    int bid = blockIdx.x;
    if (t < 32) {
        int x = 0;
        #pragma unroll
        for (int rep = 0; rep < 4; rep++) {
            int j = rep * 32 + t;
            if (j < bid && j < 98) x += g_partials[j];
        }
        #pragma unroll
        for (int o = 16; o; o >>= 1) x += __shfl_xor_sync(0xffffffffu, x, o);
        if (t == 0) base_sh = x;
    }
    int i = bid * 1024 + t;
    int v = (i < NND) ? g_counts[i] : 0;
    s[0][t] = v;
    __syncthreads();
    int pin = 0;
    #pragma unroll
    for (int off = 1; off < 1024; off <<= 1) {
        int x = s[pin][t];
        if (t >= off) x += s[pin][t - off];
        s[pin ^ 1][t] = x;
        __syncthreads();
        pin ^= 1;
    }
    if (i < NND) {
        g_offsets[i] = s[pin][t] - v + base_sh;
        g_dinv[i] = rsqrtf((float)v + 1.0f);
    }
}

// -------- CSR scatter: src only; slot from packed word; no dinv/dst reads --------
__global__ void k_scatter(const void* ei_) {
    int t4 = blockIdx.x * blockDim.x + threadIdx.x;
    if (t4 >= NED / 4) return;
    int e = t4 * 4;
    int s0, s1, s2, s3;
    if (g_is64) {
        const longlong2* ps = (const longlong2*)((const long long*)ei_ + e);
        longlong2 sa = ps[0], sb = ps[1];
        s0 = (int)sa.x; s1 = (int)sa.y; s2 = (int)sb.x; s3 = (int)sb.y;
    } else {
        int4 sa = *(const int4*)((const int*)ei_ + e);
        s0 = sa.x; s1 = sa.y; s2 = sa.z; s3 = sa.w;
    }
    int4 p = *(const int4*)&g_pk[e];
    g_csr[g_offsets[p.x & 0x1FFFF] + ((unsigned)p.x >> 17)] = s0;
    g_csr[g_offsets[p.y & 0x1FFFF] + ((unsigned)p.y >> 17)] = s1;
    g_csr[g_offsets[p.z & 0x1FFFF] + ((unsigned)p.z >> 17)] = s2;
    g_csr[g_offsets[p.w & 0x1FFFF] + ((unsigned)p.w >> 17)] = s3;
}

// ---------------- input transform: h0 = relu(x @ W_in + b_in) ----------------
__global__ void k_input(const float* __restrict__ x, const float* __restrict__ Win,
                        const float* __restrict__ bin) {
    int gid = blockIdx.x * blockDim.x + threadIdx.x;
    int node = gid >> 4;
    int q = (gid & 15) * 4;
    if (node >= NND) return;
    float4 acc = *(const float4*)&bin[q];
    #pragma unroll
    for (int k = 0; k < FIN; k++) {
        float xv = __ldg(&x[node * FIN + k]);
        float4 w = *(const float4*)&Win[k * HD + q];
        acc.x += xv * w.x; acc.y += xv * w.y; acc.z += xv * w.z; acc.w += xv * w.w;
    }
    acc.x = fmaxf(acc.x, 0.f); acc.y = fmaxf(acc.y, 0.f);
    acc.z = fmaxf(acc.z, 0.f); acc.w = fmaxf(acc.w, 0.f);
    *(float4*)&g_bufA[node * HD + q] = acc;
}

// ------- GEMM: bufH = dinv^slot-fold * (relu(BN(bufA)) @ W) as fp16 -------
// slot==0: no dinv prescale (dinv not ready on the fork; k_scale applies it later).
__global__ __launch_bounds__(128, 4) void k_gemm(const float* __restrict__ W,
                                                 const float* __restrict__ gam,
                                                 const float* __restrict__ bet,
                                                 int slot) {
    __shared__ float As[64][128];
    __shared__ float Ws[64 * 64];
    __shared__ float s_scl[64], s_sft[64];
    int t = threadIdx.x;
    if (t < 64) {
        if (slot == 0) {
            s_scl[t] = 1.f; s_sft[t] = 0.f;
        } else {
            float mu  = g_sums[slot * 128 + t] * (1.0f / (float)NND);
            float var = g_sums[slot * 128 + 64 + t] * (1.0f / (float)NND) - mu * mu;
            float scl = gam[t] * rsqrtf(var + EPSBN);
            s_scl[t] = scl;
            s_sft[t] = bet[t] - mu * scl;
        }
    }
    {
        float4* Wsv = (float4*)Ws;
        const float4* Wv = (const float4*)W;
        #pragma unroll
        for (int i = 0; i < 8; i++) Wsv[t + i * 128] = Wv[t + i * 128];
    }
    __syncthreads();

    int base = blockIdx.x * 128;
    int node = base + t;
    if (node < NND) {
        const float4* arow = (const float4*)&g_bufA[node * 64];
        #pragma unroll
        for (int kk = 0; kk < 16; kk++) {
            float4 a = arow[kk];
            int k = kk * 4;
            a.x = fmaxf(a.x * s_scl[k + 0] + s_sft[k + 0], 0.f);
            a.y = fmaxf(a.y * s_scl[k + 1] + s_sft[k + 1], 0.f);
            a.z = fmaxf(a.z * s_scl[k + 2] + s_sft[k + 2], 0.f);
            a.w = fmaxf(a.w * s_scl[k + 3] + s_sft[k + 3], 0.f);
            As[k + 0][t] = a.x; As[k + 1][t] = a.y; As[k + 2][t] = a.z; As[k + 3][t] = a.w;
        }
    } else {
        #pragma unroll
        for (int kk = 0; kk < 16; kk++) {
            int k = kk * 4;
            As[k + 0][t] = 0.f; As[k + 1][t] = 0.f; As[k + 2][t] = 0.f; As[k + 3][t] = 0.f;
        }
    }
    __syncthreads();

    int tx = t & 7, ty = t >> 3;
    int c0 = tx * 8, n0 = ty * 8;
    unsigned long long acc2[4][8];                  // [row-pair ip][col j]
    #pragma unroll
    for (int i = 0; i < 4; i++)
        #pragma unroll
        for (int j = 0; j < 8; j++) acc2[i][j] = 0ull;

    #pragma unroll 8
    for (int k = 0; k < 64; k++) {
        ulonglong2 ap0 = *(const ulonglong2*)&As[k][n0];
        ulonglong2 ap1 = *(const ulonglong2*)&As[k][n0 + 4];
        float4 w0 = *(const float4*)&Ws[k * 64 + c0];
        float4 w1 = *(const float4*)&Ws[k * 64 + c0 + 4];
        unsigned long long ap[4] = {ap0.x, ap0.y, ap1.x, ap1.y};
        float wv[8] = {w0.x, w0.y, w0.z, w0.w, w1.x, w1.y, w1.z, w1.w};
        #pragma unroll
        for (int j = 0; j < 8; j++) {
            unsigned long long wd = pack2(wv[j], wv[j]);
            #pragma unroll
            for (int ip = 0; ip < 4; ip++)
                acc2[ip][j] = fma2(ap[ip], wd, acc2[ip][j]);
        }
    }

    #pragma unroll
    for (int ip = 0; ip < 4; ip++) {
        float rA[8], rB[8];
        #pragma unroll
        for (int j = 0; j < 8; j++) {
            float2 p = unpack2(acc2[ip][j]);
            rA[j] = p.x; rB[j] = p.y;
        }
        int nA = base + n0 + 2 * ip;
        if (nA < NND) {
            float dv = (slot > 0) ? g_dinv[nA] : 1.f;
            __half2 hs[4];
            hs[0] = __float22half2_rn(make_float2(rA[0] * dv, rA[1] * dv));
            hs[1] = __float22half2_rn(make_float2(rA[2] * dv, rA[3] * dv));
            hs[2] = __float22half2_rn(make_float2(rA[4] * dv, rA[5] * dv));
            hs[3] = __float22half2_rn(make_float2(rA[6] * dv, rA[7] * dv));
            *(uint4*)&g_bufH[nA * 64 + c0] = *(const uint4*)hs;
        }
        if (nA + 1 < NND) {
            float dv = (slot > 0) ? g_dinv[nA + 1] : 1.f;
            __half2 hs[4];
            hs[0] = __float22half2_rn(make_float2(rB[0] * dv, rB[1] * dv));
            hs[1] = __float22half2_rn(make_float2(rB[2] * dv, rB[3] * dv));
            hs[2] = __float22half2_rn(make_float2(rB[4] * dv, rB[5] * dv));
            hs[3] = __float22half2_rn(make_float2(rB[6] * dv, rB[7] * dv));
            *(uint4*)&g_bufH[(nA + 1) * 64 + c0] = *(const uint4*)hs;
        }
    }
}

// ---- k_scale: bufH[n] *= dinv[n] (layer-0 fixup; gemm0 ran before dinv existed) ----
__global__ void k_scale() {
    int t = blockIdx.x * blockDim.x + threadIdx.x;   // one uint4 = 8 cols of one node
    if (t >= NND * 8) return;
    int node = t >> 3;
    float dv = g_dinv[node];
    uint4 raw = *(const uint4*)&g_bufH[(size_t)t * 8];
    __half2* hp = (__half2*)&raw;
    #pragma unroll
    for (int i = 0; i < 4; i++) {
        float2 v = __half22float2(hp[i]);
        hp[i] = __float22half2_rn(make_float2(v.x * dv, v.y * dv));
    }
    *(uint4*)&g_bufH[(size_t)t * 8] = raw;
}

// ---- aggregation (+fused BN stats): weightless half-warp gather over prescaled table ----
// out[d] = dinv[d]*(sum T[src] + T[d]) + b.  Pad lanes use src=NND (permanently-zero row).
__global__ __launch_bounds__(256) void k_agg(const float* __restrict__ bias, int slot) {
    __shared__ float s_red[128 * 9];        // col c at s_red[c*9 + warp]
    int t = threadIdx.x;
    int w = t >> 5;
    int lane = t & 31;
    int half = lane >> 4;                   // 0: even edges, 1: odd edges
    int cl = (lane & 15) * 4;               // 4-column base this lane owns
    int wid = (blockIdx.x * blockDim.x + t) >> 5;
    const __half* __restrict__ T = g_bufH;

    int beg = g_offsets[wid];
    int end = g_offsets[wid + 1];
    float a0 = 0.f, a1 = 0.f, a2 = 0.f, a3 = 0.f;

    for (int e0 = beg; e0 < end; e0 += 32) {
        int e = e0 + lane;
        int sw = (e < end) ? g_csr[e] : NND;    // NND = zero row
        int cnt = end - e0;
        #pragma unroll
        for (int jb = 0; jb < 2; jb++) {
            if (jb * 16 >= cnt) break;
            int ss[8]; uint2 hv[8];
            #pragma unroll
            for (int u = 0; u < 8; u++)
                ss[u] = __shfl_sync(0xffffffffu, sw, jb * 16 + 2 * u + half);
            #pragma unroll
            for (int u = 0; u < 8; u++)
                hv[u] = *(const uint2*)&T[ss[u] * 64 + cl];
            #pragma unroll
            for (int u = 0; u < 8; u++) {
                float2 v01 = __half22float2(((const __half2*)&hv[u])[0]);
                float2 v23 = __half22float2(((const __half2*)&hv[u])[1]);
                a0 += v01.x; a1 += v01.y; a2 += v23.x; a3 += v23.y;
            }
        }
    }

    // combine even-edge and odd-edge halves
    a0 += __shfl_xor_sync(0xffffffffu, a0, 16);
    a1 += __shfl_xor_sync(0xffffffffu, a1, 16);
    a2 += __shfl_xor_sync(0xffffffffu, a2, 16);
    a3 += __shfl_xor_sync(0xffffffffu, a3, 16);

    float dn = g_dinv[wid];
    uint2 selfraw = *(const uint2*)&T[wid * 64 + cl];
    float2 s01 = __half22float2(((const __half2*)&selfraw)[0]);
    float2 s23 = __half22float2(((const __half2*)&selfraw)[1]);
    float4 b = *(const float4*)&bias[cl];
    float4 o;
    o.x = dn * (a0 + s01.x) + b.x;
    o.y = dn * (a1 + s01.y) + b.y;
    o.z = dn * (a2 + s23.x) + b.z;
    o.w = dn * (a3 + s23.y) + b.w;
    if (half == 0) *(float4*)&g_bufA[wid * 64 + cl] = o;

    // BN stats (half 0 only), padded STS tree, 128 global atomics/block
    if (half == 0) {
        s_red[(cl + 0) * 9 + w] = o.x;
        s_red[(cl + 1) * 9 + w] = o.y;
        s_red[(cl + 2) * 9 + w] = o.z;
        s_red[(cl + 3) * 9 + w] = o.w;
        s_red[(64 + cl + 0) * 9 + w] = o.x * o.x;
        s_red[(64 + cl + 1) * 9 + w] = o.y * o.y;
        s_red[(64 + cl + 2) * 9 + w] = o.z * o.z;
        s_red[(64 + cl + 3) * 9 + w] = o.w * o.w;
    }
    __syncthreads();
    if (t < 128) {
        float s = 0.f;
        #pragma unroll
        for (int u = 0; u < 8; u++) s += s_red[t * 9 + u];
        atomicAdd(&g_sums[slot * 128 + t], s);
    }
}

// -------- classifier head: out = relu(BN(bufA) @ Wc1 + bc1) @ Wc2 + bc2 --------
__global__ void k_cls(const float* __restrict__ Wc1, const float* __restrict__ bc1,
                      const float* __restrict__ Wc2, const float* __restrict__ bc2,
                      const float* __restrict__ gam, const float* __restrict__ bet,
                      float* __restrict__ out) {
    __shared__ float w1[64 * 32];
    __shared__ float sscl[64], ssft[64], sb1[32], w2s[64], b2s[2];
    int t = threadIdx.x;
    for (int i = t; i < 2048; i += blockDim.x) w1[i] = Wc1[i];
    if (t < 64) {
        float mu  = g_sums[3 * 128 + t] * (1.0f / (float)NND);
        float var = g_sums[3 * 128 + 64 + t] * (1.0f / (float)NND) - mu * mu;
        float scl = gam[t] * rsqrtf(var + EPSBN);
        sscl[t] = scl;
        ssft[t] = bet[t] - mu * scl;
        w2s[t] = Wc2[t];
    }
    if (t < 32) sb1[t] = bc1[t];
    if (t < 2)  b2s[t] = bc2[t];
    __syncthreads();

    int wid = (blockIdx.x * blockDim.x + t) >> 5;
    if (wid >= NND) return;
    int lane = t & 31;

    float2 v = *(const float2*)&g_bufA[wid * 64 + 2 * lane];
    v.x = v.x * sscl[2 * lane + 0] + ssft[2 * lane + 0];
    v.y = v.y * sscl[2 * lane + 1] + ssft[2 * lane + 1];

    float u = sb1[lane];
    #pragma unroll
    for (int p = 0; p < 32; p++) {
        float a = __shfl_sync(0xffffffffu, v.x, p);
        float b = __shfl_sync(0xffffffffu, v.y, p);
        u = fmaf(a, w1[(2 * p + 0) * 32 + lane], u);
        u = fmaf(b, w1[(2 * p + 1) * 32 + lane], u);
    }
    u = fmaxf(u, 0.f);

    float o0 = fmaf(u, w2s[lane * 2 + 0], b2s[0] * (1.0f / 32.0f));
    float o1 = fmaf(u, w2s[lane * 2 + 1], b2s[1] * (1.0f / 32.0f));
    #pragma unroll
    for (int off = 16; off; off >>= 1) {
        o0 += __shfl_xor_sync(0xffffffffu, o0, off);
        o1 += __shfl_xor_sync(0xffffffffu, o1, off);
    }
    if (lane == 0) {
        out[wid * 2 + 0] = o0;
        out[wid * 2 + 1] = o1;
    }
}

// ---------------- host launch sequence (graph-capturable, two-stream fork-join) ----------------
extern "C" void kernel_launch(void* const* d_in, const int* in_sizes, int n_in,
                              void* d_out, int out_size) {
    const float* x     = (const float*)d_in[0];
    const void*  ei    = d_in[1];
    const float* Win   = (const float*)d_in[2];
    const float* bin   = (const float*)d_in[3];
    const float* Wg    = (const float*)d_in[4];   // [3,64,64]
    const float* bg    = (const float*)d_in[5];   // [3,64]
    const float* gamma = (const float*)d_in[6];   // [3,64]
    const float* beta  = (const float*)d_in[7];   // [3,64]
    const float* Wc1   = (const float*)d_in[8];
    const float* bc1   = (const float*)d_in[9];
    const float* Wc2   = (const float*)d_in[10];
    const float* bc2   = (const float*)d_in[11];
    float* out = (float*)d_out;

    static cudaStream_t s2 = nullptr;
    static cudaEvent_t evFork = nullptr, evScan = nullptr, evJoin = nullptr;
    if (s2 == nullptr) {
        cudaStreamCreateWithFlags(&s2, cudaStreamNonBlocking);
        cudaEventCreateWithFlags(&evFork, cudaEventDisableTiming);
        cudaEventCreateWithFlags(&evScan, cudaEventDisableTiming);
        cudaEventCreateWithFlags(&evJoin, cudaEventDisableTiming);
    }

    // Fork: side stream does input + gemm0 (unscaled), then after scan_c applies
    // the dinv prescale (k_scale) — all hidden under the CSR chain + scatter.
    cudaEventRecord(evFork, 0);
    cudaStreamWaitEvent(s2, evFork, 0);
    k_input<<<(NND * 16 + 255) / 256, 256, 0, s2>>>(x, Win, bin);
    k_gemm<<<(NND + 127) / 128, 128, 0, s2>>>(Wg, gamma, beta, 0);

    k_init<<<(NND + 255) / 256, 256>>>((const int*)ei);
    k_hist<<<(NED / 4 + 255) / 256, 256>>>(ei);
    k_scan_a<<<98, 1024>>>();
    k_scan_c<<<98, 1024>>>();
    cudaEventRecord(evScan, 0);
    cudaStreamWaitEvent(s2, evScan, 0);          // dinv ready -> layer-0 prescale on s2
    k_scale<<<(NND * 8 + 255) / 256, 256, 0, s2>>>();
    cudaEventRecord(evJoin, s2);

    k_scatter<<<(NED / 4 + 255) / 256, 256>>>(ei);
    cudaStreamWaitEvent(0, evJoin, 0);           // join before first aggregation

    k_agg<<<NND / 8, 256>>>(bg, 1);
    k_gemm<<<(NND + 127) / 128, 128>>>(Wg + 4096, gamma, beta, 1);
    k_agg<<<NND / 8, 256>>>(bg + 64, 2);
    k_gemm<<<(NND + 127) / 128, 128>>>(Wg + 8192, gamma + 64, beta + 64, 2);
    k_agg<<<NND / 8, 256>>>(bg + 128, 3);

    k_cls<<<NND / 8, 256>>>(Wc1, bc1, Wc2, bc2, gamma + 128, beta + 128, out);
}